// round 5
// baseline (speedup 1.0000x reference)
#include <cuda_runtime.h>
#include <cuda_bf16.h>
#include <cstdint>

// ============================================================================
// Problem constants
// ============================================================================
#define NQ        1024        // queries (B)
#define DDIM      512         // feature dim (K)
#define MROWS     262144      // memory bank rows
#define BANK_TILE 128         // bank rows per CTA
#define MEGA      256         // queries per pass
#define NPASS     4           // NQ / MEGA
#define KCH       4           // k-chunks of 128 int8 dims per pass
#define NCHUNK    (NPASS * KCH)

// smem layout (bytes). Row pads chosen so 8-row ldmatrix strides hit
// distinct 16B bank groups (pad mod 128 == 16).
#define BANK_RS    528                            // 512 int8 + 16 pad
#define QBUF_RS    144                            // 128 int8 + 16 pad
#define SMEM_BANK  0
#define BANK_SZ    (BANK_TILE * BANK_RS)          // 67584
#define SMEM_BSC   BANK_SZ                        // 128 floats of row scales
#define SMEM_QBUF  (BANK_SZ + 512)                // 68096 (128B aligned)
#define QBUF_SZ    (MEGA * QBUF_RS)               // 36864
#define SMEM_TOTAL (SMEM_QBUF + 2 * QBUF_SZ)      // 141824

// ============================================================================
// Scratch globals (allocation-free rule)
// ============================================================================
__device__ __align__(1024) uint8_t g_qi8[NQ * DDIM];   // quantized queries
__device__ float    g_qs[NQ];                          // query scales
__device__ unsigned g_key[NQ];                         // ordered-uint max keys

// ============================================================================
// Helpers
// ============================================================================
__device__ __forceinline__ uint32_t smem_to_u32(const void* p) {
    uint32_t a;
    asm("{ .reg .u64 t; cvta.to.shared.u64 t, %1; cvt.u32.u64 %0, t; }" : "=r"(a) : "l"(p));
    return a;
}

#define CP_ASYNC16(dst_u32, src_gptr) \
    asm volatile("cp.async.cg.shared.global [%0], [%1], 16;" :: "r"(dst_u32), "l"(src_gptr) : "memory")
#define CP_ASYNC_COMMIT() asm volatile("cp.async.commit_group;" ::: "memory")
#define CP_ASYNC_WAIT(n)  asm volatile("cp.async.wait_group %0;" :: "n"(n) : "memory")

#define LDMATRIX_X4(r0, r1, r2, r3, addr) \
    asm volatile("ldmatrix.sync.aligned.m8n8.x4.shared.b16 {%0,%1,%2,%3}, [%4];" \
        : "=r"(r0), "=r"(r1), "=r"(r2), "=r"(r3) : "r"(addr))

__device__ __forceinline__ void imma16832(int* d, const uint32_t* a, uint32_t b0, uint32_t b1) {
    asm volatile(
        "mma.sync.aligned.m16n8k32.row.col.s32.s8.s8.s32 "
        "{%0,%1,%2,%3}, {%4,%5,%6,%7}, {%8,%9}, {%0,%1,%2,%3};"
        : "+r"(d[0]), "+r"(d[1]), "+r"(d[2]), "+r"(d[3])
        : "r"(a[0]), "r"(a[1]), "r"(a[2]), "r"(a[3]), "r"(b0), "r"(b1));
}

__device__ __forceinline__ uint32_t quant_pack4(float4 v, float qf) {
    int q0 = max(-127, min(127, __float2int_rn(v.x * qf)));
    int q1 = max(-127, min(127, __float2int_rn(v.y * qf)));
    int q2 = max(-127, min(127, __float2int_rn(v.z * qf)));
    int q3 = max(-127, min(127, __float2int_rn(v.w * qf)));
    return (uint32_t)(q0 & 255) | ((uint32_t)(q1 & 255) << 8) |
           ((uint32_t)(q2 & 255) << 16) | ((uint32_t)(q3 & 255) << 24);
}

// ============================================================================
// Kernel 1: normalize + int8-quantize queries (1 warp per query)
// ============================================================================
__global__ void __launch_bounds__(128) prep_kernel(const float* __restrict__ feat) {
    const int warp = threadIdx.x >> 5;
    const int lane = threadIdx.x & 31;
    const int b    = blockIdx.x * 4 + warp;
    const float4* src = reinterpret_cast<const float4*>(feat + (size_t)b * DDIM);

    float4 v[4];
    float ss = 0.0f, mab = 0.0f;
    #pragma unroll
    for (int p = 0; p < 4; ++p) {
        v[p] = src[p * 32 + lane];
        ss += v[p].x * v[p].x + v[p].y * v[p].y + v[p].z * v[p].z + v[p].w * v[p].w;
        mab = fmaxf(mab, fmaxf(fmaxf(fabsf(v[p].x), fabsf(v[p].y)),
                               fmaxf(fabsf(v[p].z), fabsf(v[p].w))));
    }
    #pragma unroll
    for (int o = 16; o > 0; o >>= 1) {
        ss  += __shfl_xor_sync(0xFFFFFFFFu, ss, o);
        mab  = fmaxf(mab, __shfl_xor_sync(0xFFFFFFFFu, mab, o));
    }
    const float inv_n = rsqrtf(ss);
    const float mabn  = fmaxf(mab * inv_n, 1e-30f);  // maxabs of normalized row
    const float qf    = inv_n * (127.0f / mabn);

    uint32_t* dst = reinterpret_cast<uint32_t*>(g_qi8 + (size_t)b * DDIM);
    #pragma unroll
    for (int p = 0; p < 4; ++p) dst[p * 32 + lane] = quant_pack4(v[p], qf);
    if (lane == 0) {
        g_qs[b]  = mabn * (1.0f / 127.0f);
        g_key[b] = 0u;
    }
}

// ============================================================================
// Kernel 2: fused int8 GEMM (mma.sync m16n8k32.s8) + max epilogue.
//   CTA: 128 bank rows x 1024 queries, 4 passes of 256.
//   Warp grid 4(M) x 2(N), warp tile m64 x n64, int32 accumulators.
//   Per-bank-row scales applied in epilogue; max folds in registers.
// ============================================================================
__global__ void __launch_bounds__(256, 1) patchcore_main(const float* __restrict__ bank) {
    extern __shared__ char smem[];
    const uint32_t sb = smem_to_u32(smem);
    const int tid  = threadIdx.x;
    const int w    = tid >> 5;
    const int lane = tid & 31;
    const int wm   = w & 3;        // m-offset wm*64
    const int wn   = w >> 2;       // n-offset wn*64
    const size_t m0 = (size_t)blockIdx.x * BANK_TILE;

    float* s_bsc = reinterpret_cast<float*>(smem + SMEM_BSC);

    // ---- Load bank tile, per-row maxabs, quantize to int8 (warp per row) ----
    {
        const float4* src = reinterpret_cast<const float4*>(bank);
        #pragma unroll
        for (int r = 0; r < 16; ++r) {
            const int m = w + r * 8;                 // rows w, w+8, ..., w+120
            float4 v[4];
            float mab = 0.0f;
            #pragma unroll
            for (int p = 0; p < 4; ++p) {
                v[p] = src[((m0 + (size_t)m) << 7) + p * 32 + lane];
                mab = fmaxf(mab, fmaxf(fmaxf(fabsf(v[p].x), fabsf(v[p].y)),
                                       fmaxf(fabsf(v[p].z), fabsf(v[p].w))));
            }
            #pragma unroll
            for (int o = 16; o > 0; o >>= 1)
                mab = fmaxf(mab, __shfl_xor_sync(0xFFFFFFFFu, mab, o));
            mab = fmaxf(mab, 1e-30f);
            const float qf = 127.0f / mab;
            uint32_t* drow = reinterpret_cast<uint32_t*>(smem + SMEM_BANK + m * BANK_RS);
            #pragma unroll
            for (int p = 0; p < 4; ++p) drow[p * 32 + lane] = quant_pack4(v[p], qf);
            if (lane == 0) s_bsc[m] = mab * (1.0f / 127.0f);
        }
    }
    __syncthreads();

    // Preload the 16 bank-row scales this thread's accum columns map to
    float bs0[8], bs1[8];
    #pragma unroll
    for (int nt = 0; nt < 8; ++nt) {
        const int col = wn * 64 + nt * 8 + (lane & 3) * 2;
        bs0[nt] = s_bsc[col];
        bs1[nt] = s_bsc[col + 1];
    }

    // ldmatrix lane addressing (rows lane&15, 16B k-half by lane&16)
    const uint32_t lm_row = (uint32_t)(lane & 15);
    const uint32_t lm_col = (uint32_t)((lane & 16) ? 16 : 0);
    const uint32_t a_lane = ((uint32_t)(wm * 64) + lm_row) * QBUF_RS + lm_col;
    const uint32_t b_lane = sb + SMEM_BANK + ((uint32_t)(wn * 64) + lm_row) * BANK_RS + lm_col;

    const char* qbase = reinterpret_cast<const char*>(g_qi8);

    // cp.async loader: chunk j = pass*4 + kc (256 queries x 128 int8 dims)
    auto issue_qchunk = [&](int j, int buf) {
        int pass = j >> 2, kc = j & 3;
        const char* src_base = qbase + (size_t)(pass * MEGA) * DDIM + kc * 128;
        uint32_t dst_base = sb + (uint32_t)(SMEM_QBUF + buf * QBUF_SZ);
        #pragma unroll
        for (int it = 0; it < 8; ++it) {
            int idx = tid + it * 256;                // 2048 granules of 16B
            int n = idx >> 3, t = idx & 7;
            CP_ASYNC16(dst_base + (uint32_t)(n * QBUF_RS + t * 16),
                       src_base + (size_t)n * DDIM + t * 16);
        }
        CP_ASYNC_COMMIT();
    };

    issue_qchunk(0, 0);
    int j = 0;
    for (int pass = 0; pass < NPASS; ++pass) {
        int d[4][8][4];                               // [m-tile][n-tile][frag]
        #pragma unroll
        for (int mt = 0; mt < 4; ++mt)
            #pragma unroll
            for (int nt = 0; nt < 8; ++nt)
                #pragma unroll
                for (int e = 0; e < 4; ++e) d[mt][nt][e] = 0;

        for (int kc = 0; kc < KCH; ++kc, ++j) {
            const int buf = j & 1;
            if (j + 1 < NCHUNK) {
                issue_qchunk(j + 1, buf ^ 1);
                CP_ASYNC_WAIT(1);
            } else {
                CP_ASYNC_WAIT(0);
            }
            __syncthreads();

            const uint32_t abase = sb + (uint32_t)(SMEM_QBUF + buf * QBUF_SZ) + a_lane;
            const uint32_t bbase = b_lane + (uint32_t)(kc * 128);
            #pragma unroll
            for (int ks = 0; ks < 4; ++ks) {          // 4 x k32 per 128B chunk
                uint32_t a[4][4];
                #pragma unroll
                for (int mt = 0; mt < 4; ++mt)
                    LDMATRIX_X4(a[mt][0], a[mt][1], a[mt][2], a[mt][3],
                                abase + (uint32_t)(mt * 16 * QBUF_RS + ks * 32));
                #pragma unroll
                for (int bt = 0; bt < 4; ++bt) {
                    uint32_t b0, b1, b2, b3;          // b0/b2: n-tile 2bt ; b1/b3: 2bt+1
                    LDMATRIX_X4(b0, b1, b2, b3,
                                bbase + (uint32_t)(bt * 16 * BANK_RS + ks * 32));
                    #pragma unroll
                    for (int mt = 0; mt < 4; ++mt) {
                        imma16832(d[mt][2 * bt],     a[mt], b0, b2);
                        imma16832(d[mt][2 * bt + 1], a[mt], b1, b3);
                    }
                }
            }
            __syncthreads();   // all warps done with buf before refill
        }

        // ---- Epilogue: scaled max over this warp's 64 bank rows ----
        #pragma unroll
        for (int mt = 0; mt < 4; ++mt) {
            float mx0 = -3.0e38f, mx1 = -3.0e38f;     // query rows r, r+8
            #pragma unroll
            for (int nt = 0; nt < 8; ++nt) {
                mx0 = fmaxf(mx0, fmaxf((float)d[mt][nt][0] * bs0[nt],
                                       (float)d[mt][nt][1] * bs1[nt]));
                mx1 = fmaxf(mx1, fmaxf((float)d[mt][nt][2] * bs0[nt],
                                       (float)d[mt][nt][3] * bs1[nt]));
            }
            mx0 = fmaxf(mx0, __shfl_xor_sync(0xFFFFFFFFu, mx0, 1));
            mx0 = fmaxf(mx0, __shfl_xor_sync(0xFFFFFFFFu, mx0, 2));
            mx1 = fmaxf(mx1, __shfl_xor_sync(0xFFFFFFFFu, mx1, 1));
            mx1 = fmaxf(mx1, __shfl_xor_sync(0xFFFFFFFFu, mx1, 2));
            if ((lane & 3) == 0) {
                int q0 = pass * MEGA + wm * 64 + mt * 16 + (lane >> 2);
                unsigned k0 = __float_as_uint(mx0);
                k0 = (k0 & 0x80000000u) ? ~k0 : (k0 | 0x80000000u);
                unsigned k1 = __float_as_uint(mx1);
                k1 = (k1 & 0x80000000u) ? ~k1 : (k1 | 0x80000000u);
                atomicMax(&g_key[q0], k0);
                atomicMax(&g_key[q0 + 8], k1);
            }
        }
    }
}

// ============================================================================
// Kernel 3: decode keys -> min distances
// ============================================================================
__global__ void final_kernel(float* __restrict__ out) {
    int b = blockIdx.x * blockDim.x + threadIdx.x;
    if (b < NQ) {
        unsigned key = g_key[b];
        unsigned bits = (key & 0x80000000u) ? (key ^ 0x80000000u) : ~key;
        float xy = g_qs[b] * __uint_as_float(bits);
        out[b] = sqrtf(fmaxf(2.0f - 2.0f * xy, 1e-12f));
    }
}

// ============================================================================
// Launch
// ============================================================================
extern "C" void kernel_launch(void* const* d_in, const int* in_sizes, int n_in,
                              void* d_out, int out_size) {
    const float* feat = (const float*)d_in[0];
    const float* bank = (const float*)d_in[1];
    if (n_in >= 2 && in_sizes[0] != NQ * DDIM) {   // robust to input ordering
        feat = (const float*)d_in[1];
        bank = (const float*)d_in[0];
    }
    float* out = (float*)d_out;

    cudaFuncSetAttribute(patchcore_main, cudaFuncAttributeMaxDynamicSharedMemorySize, SMEM_TOTAL);

    prep_kernel<<<NQ / 4, 128>>>(feat);
    patchcore_main<<<MROWS / BANK_TILE, 256, SMEM_TOTAL>>>(bank);
    final_kernel<<<1, NQ>>>(out);
}

// round 6
// speedup vs baseline: 2.2205x; 2.2205x over previous
#include <cuda_runtime.h>
#include <cuda_fp16.h>
#include <cstdint>

// ============================================================================
// Problem constants
// ============================================================================
#define NQ        1024        // queries (B)
#define DDIM      512         // feature dim (K)
#define MROWS     262144      // memory bank rows
#define BANK_TILE 128         // bank rows per CTA
#define MEGA      128         // queries per pass
#define NPASS     8           // NQ / MEGA
#define KCH       8           // k-chunks of 64 dims per pass
#define NCHUNK    (NPASS * KCH)

// smem layout (bytes). Row pads chosen so 8-row ldmatrix strides hit
// distinct 16B bank groups (pad mod 128 == 16).
#define BANK_RS    1040                           // 512 fp16 + 16B pad
#define QBUF_RS    144                            // 64 fp16 + 16B pad
#define SMEM_BANK  0
#define BANK_SZ    (BANK_TILE * BANK_RS)          // 133120
#define SMEM_QBUF  BANK_SZ
#define QBUF_SZ    (MEGA * QBUF_RS)               // 18432
#define SMEM_TOTAL (SMEM_QBUF + 3 * QBUF_SZ)      // 188416 (ring of 3)

// ============================================================================
// Scratch globals (allocation-free rule)
// ============================================================================
__device__ __align__(1024) __half g_qh[NQ * DDIM];   // normalized fp16 queries
__device__ unsigned g_key[NQ];                       // ordered-uint max keys

// ============================================================================
// Helpers
// ============================================================================
__device__ __forceinline__ uint32_t smem_to_u32(const void* p) {
    uint32_t a;
    asm("{ .reg .u64 t; cvta.to.shared.u64 t, %1; cvt.u32.u64 %0, t; }" : "=r"(a) : "l"(p));
    return a;
}

#define CP_ASYNC16(dst_u32, src_gptr) \
    asm volatile("cp.async.cg.shared.global [%0], [%1], 16;" :: "r"(dst_u32), "l"(src_gptr) : "memory")
#define CP_ASYNC_COMMIT() asm volatile("cp.async.commit_group;" ::: "memory")
#define CP_ASYNC_WAIT(n)  asm volatile("cp.async.wait_group %0;" :: "n"(n) : "memory")

#define LDMATRIX_X4(r0, r1, r2, r3, addr) \
    asm volatile("ldmatrix.sync.aligned.m8n8.x4.shared.b16 {%0,%1,%2,%3}, [%4];" \
        : "=r"(r0), "=r"(r1), "=r"(r2), "=r"(r3) : "r"(addr))

// fp16 inputs, fp16 accumulate: D(2 x f16x2) = A(4) * B(2) + D
__device__ __forceinline__ void mma16816h(uint32_t* d, const uint32_t* a, uint32_t b0, uint32_t b1) {
    asm volatile(
        "mma.sync.aligned.m16n8k16.row.col.f16.f16.f16.f16 "
        "{%0,%1}, {%2,%3,%4,%5}, {%6,%7}, {%0,%1};"
        : "+r"(d[0]), "+r"(d[1])
        : "r"(a[0]), "r"(a[1]), "r"(a[2]), "r"(a[3]), "r"(b0), "r"(b1));
}

// ============================================================================
// Kernel 1: normalize queries -> fp16 buffer; init max keys
// ============================================================================
__global__ void __launch_bounds__(128) prep_kernel(const float* __restrict__ feat) {
    const int warp = threadIdx.x >> 5;
    const int lane = threadIdx.x & 31;
    const int b    = blockIdx.x * 4 + warp;
    const float4* src = reinterpret_cast<const float4*>(feat + (size_t)b * DDIM);

    float4 v[4];
    float ss = 0.0f;
    #pragma unroll
    for (int p = 0; p < 4; ++p) {
        v[p] = src[p * 32 + lane];
        ss += v[p].x * v[p].x + v[p].y * v[p].y + v[p].z * v[p].z + v[p].w * v[p].w;
    }
    #pragma unroll
    for (int o = 16; o > 0; o >>= 1) ss += __shfl_xor_sync(0xFFFFFFFFu, ss, o);
    const float inv = rsqrtf(ss);

    __half2* dst = reinterpret_cast<__half2*>(g_qh + (size_t)b * DDIM);
    #pragma unroll
    for (int p = 0; p < 4; ++p) {
        dst[(p * 32 + lane) * 2 + 0] = __floats2half2_rn(v[p].x * inv, v[p].y * inv);
        dst[(p * 32 + lane) * 2 + 1] = __floats2half2_rn(v[p].z * inv, v[p].w * inv);
    }
    if (lane == 0) g_key[b] = 0u;
}

// ============================================================================
// Kernel 2: fused fp16 GEMM (mma.sync, f16 accumulate) + max epilogue.
//   CTA: 128 bank rows x 1024 queries, 8 passes of 128.
//   Warp grid 4(M) x 2(N): warp tile m32 x n64, f16x2 accumulators.
//   Ring-3 query buffer -> single __syncthreads per k-chunk.
// ============================================================================
__global__ void __launch_bounds__(256, 1) patchcore_main(const float* __restrict__ bank) {
    extern __shared__ char smem[];
    const uint32_t sb = smem_to_u32(smem);
    const int tid  = threadIdx.x;
    const int w    = tid >> 5;
    const int lane = tid & 31;
    const int wm   = w & 3;        // m-offset wm*32
    const int wn   = w >> 2;       // n-offset wn*64
    const size_t m0 = (size_t)blockIdx.x * BANK_TILE;

    // ---- Load bank tile (128 x 512 fp32) -> fp16, padded rows ----
    {
        const float4* src = reinterpret_cast<const float4*>(bank);
        #pragma unroll 4
        for (int idx = tid; idx < BANK_TILE * (DDIM / 4); idx += 256) {
            int m = idx >> 7;           // bank row within tile
            int c4 = idx & 127;         // float4 index within row
            float4 v = src[((m0 + (size_t)m) << 7) + c4];
            __half2 lo = __floats2half2_rn(v.x, v.y);
            __half2 hi = __floats2half2_rn(v.z, v.w);
            uint2 p;
            p.x = *reinterpret_cast<uint32_t*>(&lo);
            p.y = *reinterpret_cast<uint32_t*>(&hi);
            *reinterpret_cast<uint2*>(smem + (SMEM_BANK + m * BANK_RS + c4 * 8)) = p;
        }
    }

    // ldmatrix lane addressing (rows lane&15, 16B k-half by lane&16)
    const uint32_t lm_row = (uint32_t)(lane & 15);
    const uint32_t lm_col = (uint32_t)((lane & 16) ? 16 : 0);
    const uint32_t a_lane = ((uint32_t)(wm * 32) + lm_row) * QBUF_RS + lm_col;
    const uint32_t b_lane = sb + SMEM_BANK + ((uint32_t)(wn * 64) + lm_row) * BANK_RS + lm_col;

    const char* qbase = reinterpret_cast<const char*>(g_qh);

    // cp.async loader: chunk j = pass*8 + kc (128 queries x 64 fp16 dims)
    auto issue_qchunk = [&](int j, int slot) {
        int pass = j >> 3, kc = j & 7;
        const char* src_base = qbase + (size_t)(pass * MEGA) * (DDIM * 2) + kc * 128;
        uint32_t dst_base = sb + (uint32_t)(SMEM_QBUF + slot * QBUF_SZ);
        #pragma unroll
        for (int it = 0; it < 4; ++it) {
            int idx = tid + it * 256;                 // 1024 granules of 16B
            int n = idx >> 3, t = idx & 7;
            CP_ASYNC16(dst_base + (uint32_t)(n * QBUF_RS + t * 16),
                       src_base + (size_t)n * (DDIM * 2) + t * 16);
        }
        CP_ASYNC_COMMIT();
    };

    issue_qchunk(0, 0);
    issue_qchunk(1, 1);
    __syncthreads();   // bank tile visible to all warps

    int j = 0;
    for (int pass = 0; pass < NPASS; ++pass) {
        uint32_t d[2][8][2];                           // f16x2 accum [m-tile][n-tile][row]
        #pragma unroll
        for (int mt = 0; mt < 2; ++mt)
            #pragma unroll
            for (int nt = 0; nt < 8; ++nt) { d[mt][nt][0] = 0u; d[mt][nt][1] = 0u; }

        for (int kc = 0; kc < KCH; ++kc, ++j) {
            const int slot = j % 3;
            if (j == NCHUNK - 1) CP_ASYNC_WAIT(0); else CP_ASYNC_WAIT(1);
            __syncthreads();   // chunk j visible; all warps past MMA(j-1)
            if (j + 2 < NCHUNK) issue_qchunk(j + 2, (j + 2) % 3);

            const uint32_t abase = sb + (uint32_t)(SMEM_QBUF + slot * QBUF_SZ) + a_lane;
            const uint32_t bbase = b_lane + (uint32_t)(j & 7) * 128;
            #pragma unroll
            for (int ks = 0; ks < 4; ++ks) {           // 4 x k16 per 64-dim chunk
                uint32_t a[2][4];
                #pragma unroll
                for (int mt = 0; mt < 2; ++mt)
                    LDMATRIX_X4(a[mt][0], a[mt][1], a[mt][2], a[mt][3],
                                abase + (uint32_t)(mt * 16 * QBUF_RS + ks * 32));
                #pragma unroll
                for (int bt = 0; bt < 4; ++bt) {
                    uint32_t b0, b1, b2, b3;           // b0/b2: n-tile 2bt ; b1/b3: 2bt+1
                    LDMATRIX_X4(b0, b1, b2, b3,
                                bbase + (uint32_t)(bt * 16 * BANK_RS + ks * 32));
                    #pragma unroll
                    for (int mt = 0; mt < 2; ++mt) {
                        mma16816h(d[mt][2 * bt],     a[mt], b0, b2);
                        mma16816h(d[mt][2 * bt + 1], a[mt], b1, b3);
                    }
                }
            }
        }

        // ---- Epilogue: max over this warp's 64 bank rows per query ----
        #pragma unroll
        for (int mt = 0; mt < 2; ++mt) {
            __half2 h0 = *reinterpret_cast<__half2*>(&d[mt][0][0]);
            __half2 h1 = *reinterpret_cast<__half2*>(&d[mt][0][1]);
            #pragma unroll
            for (int nt = 1; nt < 8; ++nt) {
                h0 = __hmax2(h0, *reinterpret_cast<__half2*>(&d[mt][nt][0]));
                h1 = __hmax2(h1, *reinterpret_cast<__half2*>(&d[mt][nt][1]));
            }
            float mx0 = fmaxf(__low2float(h0), __high2float(h0));   // query row r
            float mx1 = fmaxf(__low2float(h1), __high2float(h1));   // query row r+8
            mx0 = fmaxf(mx0, __shfl_xor_sync(0xFFFFFFFFu, mx0, 1));
            mx0 = fmaxf(mx0, __shfl_xor_sync(0xFFFFFFFFu, mx0, 2));
            mx1 = fmaxf(mx1, __shfl_xor_sync(0xFFFFFFFFu, mx1, 1));
            mx1 = fmaxf(mx1, __shfl_xor_sync(0xFFFFFFFFu, mx1, 2));
            if ((lane & 3) == 0) {
                int q0 = pass * MEGA + wm * 32 + mt * 16 + (lane >> 2);
                unsigned k0 = __float_as_uint(mx0);
                k0 = (k0 & 0x80000000u) ? ~k0 : (k0 | 0x80000000u);
                unsigned k1 = __float_as_uint(mx1);
                k1 = (k1 & 0x80000000u) ? ~k1 : (k1 | 0x80000000u);
                atomicMax(&g_key[q0], k0);
                atomicMax(&g_key[q0 + 8], k1);
            }
        }
    }
}

// ============================================================================
// Kernel 3: decode keys -> min distances
// ============================================================================
__global__ void final_kernel(float* __restrict__ out) {
    int b = blockIdx.x * blockDim.x + threadIdx.x;
    if (b < NQ) {
        unsigned key = g_key[b];
        unsigned bits = (key & 0x80000000u) ? (key ^ 0x80000000u) : ~key;
        float xy = __uint_as_float(bits);
        out[b] = sqrtf(fmaxf(2.0f - 2.0f * xy, 1e-12f));
    }
}

// ============================================================================
// Launch
// ============================================================================
extern "C" void kernel_launch(void* const* d_in, const int* in_sizes, int n_in,
                              void* d_out, int out_size) {
    const float* feat = (const float*)d_in[0];
    const float* bank = (const float*)d_in[1];
    if (n_in >= 2 && in_sizes[0] != NQ * DDIM) {   // robust to input ordering
        feat = (const float*)d_in[1];
        bank = (const float*)d_in[0];
    }
    float* out = (float*)d_out;

    cudaFuncSetAttribute(patchcore_main, cudaFuncAttributeMaxDynamicSharedMemorySize, SMEM_TOTAL);

    prep_kernel<<<NQ / 4, 128>>>(feat);
    patchcore_main<<<MROWS / BANK_TILE, 256, SMEM_TOTAL>>>(bank);
    final_kernel<<<1, NQ>>>(out);
}